// round 2
// baseline (speedup 1.0000x reference)
#include <cuda_runtime.h>

// ---------------------------------------------------------------------------
// HyperAttention, GB300 round 1: fused block-diagonal + sampled-residual
// attention (joint softmax), fp32 with packed f32x2 FFMA.
//
// Shapes (fixed by the problem): B=2, H=16, N=8192, D=64, 7 projections,
// BLOCK=256, SAMPLE=256 -> per (b,h): 32 query blocks x (256 block keys +
// 256 sampled keys).
// ---------------------------------------------------------------------------

#define BH      32          // B*H
#define NSEQ    8192
#define DIM     64
#define NPROJ   7
#define NBUCK   128         // 2^NPROJ
#define NSEG    128
#define SEGLEN  64          // NSEG*SEGLEN == NSEQ
#define ST      130         // padded segment-hist stride (uint16) -> conflict-free
#define LOG32   3.4657359027997265f
#define BIGNEG  (-1e30f)

typedef unsigned long long ull;

// scratch (device globals; no allocations allowed)
__device__ unsigned char g_hash[2][BH * NSEQ];
__device__ int           g_idx[2][BH * NSEQ];   // [0]=q_idx, [1]=k_idx

// ---- packed fp32x2 helpers (sm_100+ PTX) ----------------------------------
__device__ __forceinline__ ull pk2(float a, float b) {
    ull r; asm("mov.b64 %0, {%1, %2};" : "=l"(r) : "f"(a), "f"(b)); return r;
}
__device__ __forceinline__ void upk2(ull x, float& a, float& b) {
    asm("mov.b64 {%0, %1}, %2;" : "=f"(a), "=f"(b) : "l"(x));
}
__device__ __forceinline__ ull f2fma(ull a, ull b, ull c) {
    ull d; asm("fma.rn.f32x2 %0, %1, %2, %3;" : "=l"(d) : "l"(a), "l"(b), "l"(c));
    return d;
}
__device__ __forceinline__ ull f2mul(ull a, ull b) {
    ull d; asm("mul.rn.f32x2 %0, %1, %2;" : "=l"(d) : "l"(a), "l"(b));
    return d;
}

// ---------------------------------------------------------------------------
// Kernel 1: angular LSH hash.  One warp per row (cooperative dot products).
// hash = gray(code), gray(c) = c ^ (c>>1)   (== PERM lookup in the reference)
// ---------------------------------------------------------------------------
__global__ void hash_kernel(const float* __restrict__ x,
                            const float* __restrict__ proj, int which) {
    unsigned char* out = g_hash[which];
    const int lane = threadIdx.x & 31;
    const int gw   = (blockIdx.x * blockDim.x + threadIdx.x) >> 5;
    const int nw   = (gridDim.x * blockDim.x) >> 5;

    float pj0[NPROJ], pj1[NPROJ];
#pragma unroll
    for (int r = 0; r < NPROJ; r++) {
        pj0[r] = proj[(2 * lane)     * NPROJ + r];
        pj1[r] = proj[(2 * lane + 1) * NPROJ + r];
    }

    const int total = BH * NSEQ;
    for (int row = gw; row < total; row += nw) {
        float2 x2 = *(const float2*)(x + (size_t)row * DIM + 2 * lane);
        float p[NPROJ];
#pragma unroll
        for (int r = 0; r < NPROJ; r++)
            p[r] = x2.x * pj0[r] + x2.y * pj1[r];
#pragma unroll
        for (int off = 16; off > 0; off >>= 1) {
#pragma unroll
            for (int r = 0; r < NPROJ; r++)
                p[r] += __shfl_xor_sync(0xffffffffu, p[r], off);
        }
        if (lane == 0) {
            int c = 0;
#pragma unroll
            for (int r = 0; r < NPROJ; r++)
                c |= (p[r] > 0.0f ? 1 : 0) << r;
            out[row] = (unsigned char)(c ^ (c >> 1));
        }
    }
}

// ---------------------------------------------------------------------------
// Kernel 2: per-(b,h) stable counting sort (exactly matches stable argsort).
// 128 threads, 128 segments of 64 elements, 128 buckets.
// ---------------------------------------------------------------------------
__global__ void sort_kernel(int which) {
    __shared__ unsigned char  h[NSEQ];
    __shared__ unsigned short seg[NSEG * ST];
    __shared__ int base[NBUCK];
    __shared__ int total[NBUCK];

    const int bh = blockIdx.x;
    const int t  = threadIdx.x;           // 0..127
    const unsigned char* hp = g_hash[which] + bh * NSEQ;
    int* op = g_idx[which] + bh * NSEQ;

    for (int i = t; i < NSEQ; i += NSEG) h[i] = hp[i];
    for (int i = t; i < NSEG * ST; i += NSEG) seg[i] = 0;
    __syncthreads();

    {   // per-segment histogram (sequential within segment => stable)
        unsigned short* row = seg + t * ST;
        const int b0 = t * SEGLEN;
        for (int k2 = 0; k2 < SEGLEN; k2++) row[h[b0 + k2]]++;
    }
    __syncthreads();

    {   // exclusive prefix over segments, per bucket (thread t = bucket t)
        int run = 0;
        for (int s = 0; s < NSEG; s++) {
            int c = seg[s * ST + t];
            seg[s * ST + t] = (unsigned short)run;
            run += c;
        }
        total[t] = run;
    }
    __syncthreads();

    if (t == 0) {   // exclusive scan of bucket totals
        int run = 0;
        for (int vv = 0; vv < NBUCK; vv++) { base[vv] = run; run += total[vv]; }
    }
    __syncthreads();

    {   // stable placement
        unsigned short* row = seg + t * ST;
        const int b0 = t * SEGLEN;
        for (int k2 = 0; k2 < SEGLEN; k2++) {
            int i = b0 + k2;
            int vv = h[i];
            int pos = base[vv] + row[vv];
            row[vv]++;
            op[pos] = i;
        }
    }
}

// ---------------------------------------------------------------------------
// Kernel 3: fused attention.
// Grid (32 qblocks, 32 bh), 256 threads = one sorted query per thread.
// Keys: chunk 0..3 = this block's 256 sorted keys (bias 0);
//       chunk 4..7 = 256 sampled keys (bias = +log 32, or -1e30 if the
//       sampled key's block == this query block).
// Online softmax over all 512 keys == reference's two-part LSE combine.
// ---------------------------------------------------------------------------
#define CHUNK 64
#define GROUP 8

__global__ __launch_bounds__(256, 1)
void attn_kernel(const float* __restrict__ q, const float* __restrict__ k,
                 const float* __restrict__ v, const int* __restrict__ sampled,
                 float* __restrict__ out) {
    __shared__ __align__(16) float Ksm[CHUNK][DIM];
    __shared__ __align__(16) float Vsm[CHUNK][DIM];
    __shared__ float addv[CHUNK];

    const int qb = blockIdx.x;
    const int bh = blockIdx.y;
    const int t  = threadIdx.x;

    const size_t bhBase = (size_t)bh * NSEQ;
    const int* qidx = g_idx[0] + bhBase;
    const int* kidx = g_idx[1] + bhBase;
    const int* smp  = sampled + bh * 256;

    const int qrow = qidx[qb * 256 + t];
    const float* qp = q + (bhBase + qrow) * DIM;

    // load query, pre-scaled by D^-0.5 = 0.125 (exact power of two)
    ull q2[32];
#pragma unroll
    for (int u = 0; u < 16; u++) {
        float4 f = ((const float4*)qp)[u];
        q2[2 * u]     = pk2(f.x * 0.125f, f.y * 0.125f);
        q2[2 * u + 1] = pk2(f.z * 0.125f, f.w * 0.125f);
    }

    float m = -__int_as_float(0x7f800000);  // -inf
    float l = 0.0f;
    ull acc[32];
#pragma unroll
    for (int i = 0; i < 32; i++) acc[i] = 0ull;

#pragma unroll 1
    for (int c = 0; c < 8; c++) {
        __syncthreads();
        {   // cooperative load of 64 (key,value) rows; 4 threads per row
            const int j   = t >> 2;
            const int sub = t & 3;
            const int kk  = c * CHUNK + j;
            int srow; float ad;
            if (kk < 256) { srow = qb * 256 + kk; ad = 0.0f; }
            else {
                int sj = smp[kk - 256];
                srow = sj;
                ad = ((sj >> 8) == qb) ? BIGNEG : LOG32;
            }
            const int krow = kidx[srow];
            const float4* kr = (const float4*)(k + (bhBase + krow) * DIM) + sub * 4;
            const float4* vr = (const float4*)(v + (bhBase + krow) * DIM) + sub * 4;
            float4* kd = (float4*)&Ksm[j][sub * 16];
            float4* vd = (float4*)&Vsm[j][sub * 16];
#pragma unroll
            for (int u = 0; u < 4; u++) { kd[u] = kr[u]; vd[u] = vr[u]; }
            if (sub == 0) addv[j] = ad;
        }
        __syncthreads();

#pragma unroll 1
        for (int g = 0; g < CHUNK / GROUP; g++) {
            float s[GROUP];
#pragma unroll
            for (int jj = 0; jj < GROUP; jj++) {
                const int jr = g * GROUP + jj;
                const ulonglong2* kp = (const ulonglong2*)&Ksm[jr][0];
                ull t0 = 0ull, t1 = 0ull;
#pragma unroll
                for (int dd = 0; dd < 16; dd++) {
                    ulonglong2 kv = kp[dd];
                    t0 = f2fma(q2[2 * dd],     kv.x, t0);
                    t1 = f2fma(q2[2 * dd + 1], kv.y, t1);
                }
                float a, b, cc, dd2;
                upk2(t0, a, b); upk2(t1, cc, dd2);
                s[jj] = (a + cc) + (b + dd2) + addv[jr];
            }
            float gm = s[0];
#pragma unroll
            for (int jj = 1; jj < GROUP; jj++) gm = fmaxf(gm, s[jj]);
            const float mn = fmaxf(m, gm);
            const float sc = __expf(m - mn);
            l *= sc;
            const ull sc2 = pk2(sc, sc);
#pragma unroll
            for (int d = 0; d < 32; d++) acc[d] = f2mul(acc[d], sc2);
#pragma unroll
            for (int jj = 0; jj < GROUP; jj++) {
                const int jr = g * GROUP + jj;
                const float p = __expf(s[jj] - mn);
                l += p;
                const ull p2 = pk2(p, p);
                const ulonglong2* vp = (const ulonglong2*)&Vsm[jr][0];
#pragma unroll
                for (int dd = 0; dd < 16; dd++) {
                    ulonglong2 vv = vp[dd];
                    acc[2 * dd]     = f2fma(p2, vv.x, acc[2 * dd]);
                    acc[2 * dd + 1] = f2fma(p2, vv.y, acc[2 * dd + 1]);
                }
            }
            m = mn;
        }
    }

    // normalize + scatter back to original query order (gather by q_idx_inv
    // == scatter by q_idx)
    const float inv = 1.0f / l;
    float* op = out + (bhBase + qrow) * DIM;
#pragma unroll
    for (int d = 0; d < 32; d++) {
        float a, b; upk2(acc[d], a, b);
        op[2 * d]     = a * inv;
        op[2 * d + 1] = b * inv;
    }
}

// ---------------------------------------------------------------------------
extern "C" void kernel_launch(void* const* d_in, const int* in_sizes, int n_in,
                              void* d_out, int out_size) {
    (void)in_sizes; (void)n_in; (void)out_size;
    const float* q    = (const float*)d_in[0];
    const float* k    = (const float*)d_in[1];
    const float* v    = (const float*)d_in[2];
    const float* proj = (const float*)d_in[3];
    const int*   smp  = (const int*)d_in[4];
    float* out = (float*)d_out;

    hash_kernel<<<512, 256>>>(q, proj, 0);
    hash_kernel<<<512, 256>>>(k, proj, 1);
    sort_kernel<<<32, 128>>>(0);
    sort_kernel<<<32, 128>>>(1);
    attn_kernel<<<dim3(32, 32), 256>>>(q, k, v, smp, out);
}